// round 9
// baseline (speedup 1.0000x reference)
#include <cuda_runtime.h>

#define BB   16
#define TT   4096
#define FEAT 256
#define KW   5
#define CH   128           // seq_scan chunk (steps)
#define GRP  16            // checkpoint group
#define NGRP (TT / GRP)    // 256 groups per batch

// Scratch (no allocations allowed).
__device__ float  g_weff[FEAT * KW];
__device__ float  g_bias;
__device__ float  g_alphas[BB * TT];     // [b][t] for emit/compact
__device__ float  g_alphasT[TT * BB];    // [t][b] for seq_scan (coalesced)
__device__ float  g_chk[NGRP * BB];      // acc checkpoint before each 16-group
__device__ float  g_accb[BB * TT];       // acc BEFORE step t, [b][t] (by compact)
__device__ int    g_ft[BB * TT];
__device__ int2   g_seg[BB * TT];
__device__ int    g_n[BB];
__device__ int    g_nofire[BB];

#define ACCB(t, b) g_accb[(size_t)(b) * TT + (t)]

// ---------------------------------------------------------------------------
// Kernel 1: fold lin_w into conv_w  ->  w_eff[c,k] = sum_o lin_w[o]*conv_w[o,c,k]
// ---------------------------------------------------------------------------
__global__ void fold_kernel(const float* __restrict__ conv_w,
                            const float* __restrict__ conv_b,
                            const float* __restrict__ lin_w,
                            const float* __restrict__ lin_b) {
    int j = blockIdx.x * blockDim.x + threadIdx.x;   // j = c*KW + k
    if (j < FEAT * KW) {
        float s = 0.f;
#pragma unroll 4
        for (int o = 0; o < FEAT; ++o)
            s = fmaf(lin_w[o], conv_w[o * (FEAT * KW) + j], s);
        g_weff[j] = s;
    }
    if (blockIdx.x == 0) {
        __shared__ float sh[256];
        sh[threadIdx.x] = conv_b[threadIdx.x] * lin_w[threadIdx.x];
        __syncthreads();
        for (int ofs = 128; ofs > 0; ofs >>= 1) {
            if ((int)threadIdx.x < ofs) sh[threadIdx.x] += sh[threadIdx.x + ofs];
            __syncthreads();
        }
        if (threadIdx.x == 0) g_bias = sh[0] + lin_b[0];
    }
}

// ---------------------------------------------------------------------------
// Kernel 2 (fused conv+linear+sigmoid): alphas[b,t] = sigmoid(bias +
// sum_c sum_k w_eff[c,k] x[b, t+k-2, c]).
// ---------------------------------------------------------------------------
#define RPB 32
#define SROWS (RPB + 4)

__global__ __launch_bounds__(256) void logit_kernel(const float* __restrict__ x) {
    __shared__ float4 sx[SROWS][FEAT / 4];   // 36 KB

    int blk = blockIdx.x;                 // 0 .. BB*(TT/RPB)-1
    int b = blk >> 7;                     // TT/RPB = 128 blocks per batch
    int r0 = (blk & 127) * RPB;
    int tid = threadIdx.x;
    int lane = tid & 31;
    int w = tid >> 5;

    const float* xb = x + (size_t)b * TT * FEAT;

#pragma unroll
    for (int i = 0; i < SROWS; ++i) {
        int gr = r0 - 2 + i;
        float v = 0.f;
        if (gr >= 0 && gr < TT) v = xb[(size_t)gr * FEAT + tid];
        ((float*)sx[i])[tid] = v;
    }
    __syncthreads();

    float wr[8][KW];
#pragma unroll
    for (int j = 0; j < 8; ++j) {
        int c = (j < 4) ? (4 * lane + j) : (124 + 4 * lane + j);
#pragma unroll
        for (int k = 0; k < KW; ++k) wr[j][k] = g_weff[c * KW + k];
    }
    float bias = g_bias;

#pragma unroll
    for (int r = 0; r < 4; ++r) {
        int j = w * 4 + r;
        float s = 0.f;
#pragma unroll
        for (int k = 0; k < KW; ++k) {
            float4 A = sx[j + k][lane];
            float4 B = sx[j + k][lane + 32];
            s = fmaf(A.x, wr[0][k], s);
            s = fmaf(A.y, wr[1][k], s);
            s = fmaf(A.z, wr[2][k], s);
            s = fmaf(A.w, wr[3][k], s);
            s = fmaf(B.x, wr[4][k], s);
            s = fmaf(B.y, wr[5][k], s);
            s = fmaf(B.z, wr[6][k], s);
            s = fmaf(B.w, wr[7][k], s);
        }
#pragma unroll
        for (int ofs = 16; ofs > 0; ofs >>= 1)
            s += __shfl_xor_sync(0xffffffffu, s, ofs);
        if (lane == 0) {
            int t = r0 + j;
            float v = 1.f / (1.f + expf(-(s + bias)));
            g_alphas[(size_t)b * TT + t] = v;
            g_alphasT[t * BB + b] = v;
        }
    }
}

// ---------------------------------------------------------------------------
// Kernel 3: sequential alpha scan — minimal body. 128-step chunks double-
// buffered in smem; a1 computed FIRST (in-order-issue hint: FSETP can issue
// right after acc_new, shortening the effective chain).
// ---------------------------------------------------------------------------
__global__ __launch_bounds__(32, 1) void seq_scan_kernel() {
    __shared__ float sa[2][CH * BB];          // 2 x 8KB
    const int lane = threadIdx.x;
    const int b = lane & 15;

    const float4* src = (const float4*)g_alphasT;  // CH*BB/4 = 512 float4/chunk

    {
        float4 v[16];
#pragma unroll
        for (int i = 0; i < 16; ++i) v[i] = src[lane + 32 * i];
#pragma unroll
        for (int i = 0; i < 16; ++i) ((float4*)sa[0])[lane + 32 * i] = v[i];
    }
    __syncwarp();

    float acc = 0.f;
    int buf = 0;

    for (int c = 0; c < TT / CH; ++c) {
        float4 pf[16];
        if (c + 1 < TT / CH) {
            const float4* s2 = src + (c + 1) * (CH * BB / 4);
#pragma unroll
            for (int i = 0; i < 16; ++i) pf[i] = s2[lane + 32 * i];
        }

        if (lane < 16) {
            const float* s = sa[buf] + b;
#pragma unroll
            for (int sub = 0; sub < CH / GRP; ++sub) {
                g_chk[(c * (CH / GRP) + sub) * BB + b] = acc;   // checkpoint
#pragma unroll
                for (int j = 0; j < GRP; ++j) {
                    float a = s[(sub * GRP + j) * BB];          // LDS, imm offset
                    float a1 = 1.0f - acc;                      // off-chain first
                    float acc_new = acc + a;
                    float a2 = a - a1;
                    acc = (acc_new >= 1.0f) ? a2 : acc_new;
                }
            }
        }

        if (c + 1 < TT / CH) {
            buf ^= 1;
            __syncwarp();
#pragma unroll
            for (int i = 0; i < 16; ++i)
                ((float4*)sa[buf])[lane + 32 * i] = pf[i];
            __syncwarp();
        }
    }
}

// ---------------------------------------------------------------------------
// Kernel 4: compact. Thread g replays 16-step group g from its checkpoint
// (IDENTICAL fp ops -> bit-identical fire/acc), coalesced acc_before store,
// shfl-based prefix (2 barriers instead of 16), segment table build.
// ---------------------------------------------------------------------------
__global__ __launch_bounds__(256) void compact_kernel() {
    int b = blockIdx.x;
    int g = threadIdx.x;                       // 0..255
    int lane = g & 31;
    int wid = g >> 5;
    __shared__ int wsum[8];
    __shared__ int ntot;

    int base = g * GRP;
    float acc = g_chk[g * BB + b];
    const float* ab = g_alphas + (size_t)b * TT + base;

    float accs[GRP];
    unsigned m = 0u;
#pragma unroll
    for (int j = 0; j < GRP; ++j) {
        float a = ab[j];
        accs[j] = acc;
        float a1 = 1.0f - acc;
        float acc_new = acc + a;
        float a2 = a - a1;
        bool fire = (acc_new >= 1.0f);
        if (fire) m |= (1u << j);
        acc = fire ? a2 : acc_new;
    }
    float4* dst = (float4*)(g_accb + (size_t)b * TT + base);
#pragma unroll
    for (int q = 0; q < 4; ++q)
        dst[q] = make_float4(accs[q * 4], accs[q * 4 + 1],
                             accs[q * 4 + 2], accs[q * 4 + 3]);

    int cnt = __popc(m);

    // warp inclusive scan
    int v = cnt;
#pragma unroll
    for (int ofs = 1; ofs < 32; ofs <<= 1) {
        int u = __shfl_up_sync(0xffffffffu, v, ofs);
        if (lane >= ofs) v += u;
    }
    if (lane == 31) wsum[wid] = v;
    __syncthreads();
    if (wid == 0) {
        int wv = (lane < 8) ? wsum[lane] : 0;
#pragma unroll
        for (int ofs = 1; ofs < 8; ofs <<= 1) {
            int u = __shfl_up_sync(0xffffffffu, wv, ofs);
            if (lane >= ofs) wv += u;
        }
        if (lane < 8) wsum[lane] = wv;
        if (lane == 7) ntot = wv;
    }
    __syncthreads();

    int n = ntot;
    int rank = ((wid > 0) ? wsum[wid - 1] : 0) + v - cnt;  // exclusive prefix
    const int wbase = b * TT;

    unsigned mm = m;
    while (mm) {
        int i = __ffs(mm) - 1;
        mm &= mm - 1;
        g_ft[wbase + rank] = base + i;
        ++rank;
    }
    __syncthreads();

    if (n == 0) {
        if (g == 0) {
            g_ft[wbase] = TT - 1;
            g_seg[wbase] = make_int2(-1, TT - 1);
            g_n[b] = 1;
            g_nofire[b] = 1;
        }
        return;
    }

    for (int j = g; j < n; j += 256) {
        int s = (j == 0) ? -1 : g_ft[wbase + j - 1];
        g_seg[wbase + j] = make_int2(s, g_ft[wbase + j]);
    }
    if (g == 0) {
        g_n[b] = n;
        g_nofire[b] = 0;
    }
}

// ---------------------------------------------------------------------------
// Kernel 5: emission. Tail rows are pre-zeroed by the forked memset, so only
// rows j < n are written. Weights recomputed from acc_before with the
// reference's exact fp ops. lens written here (after the memset join).
// ---------------------------------------------------------------------------
__global__ __launch_bounds__(FEAT) void emit_kernel(const float* __restrict__ x,
                                                    float* __restrict__ out,
                                                    float* __restrict__ lens,
                                                    int write_len) {
    int b = blockIdx.x;
    int d = threadIdx.x;
    int n = g_n[b];
    int nofire = g_nofire[b];
    const float* xb = x + (size_t)b * TT * FEAT;
    const float* ab = g_alphas + (size_t)b * TT;
    const int wbase = b * TT;
    float* ob = out + (size_t)b * TT * FEAT;

    if (write_len && blockIdx.y == 0 && d == 0) lens[b] = (float)n;

    for (int j = blockIdx.y; j < n; j += gridDim.y) {
        int2 se = g_seg[wbase + j];
        float accv = 0.f;
        int u0 = 0;
        if (se.x >= 0) {
            float a2 = ab[se.x] - (1.0f - ACCB(se.x, b));
            accv = a2 * xb[(size_t)se.x * FEAT + d];
            u0 = se.x + 1;
        }
        for (int u = u0; u < se.y; ++u)
            accv = fmaf(ab[u], xb[(size_t)u * FEAT + d], accv);
        float we = nofire ? ab[se.y] : (1.0f - ACCB(se.y, b));
        accv = fmaf(we, xb[(size_t)se.y * FEAT + d], accv);
        ob[(size_t)j * FEAT + d] = accv;
    }
}

// ---------------------------------------------------------------------------
extern "C" void kernel_launch(void* const* d_in, const int* in_sizes, int n_in,
                              void* d_out, int out_size) {
    const float* x      = (const float*)d_in[0];
    const float* conv_w = (const float*)d_in[1];
    const float* conv_b = (const float*)d_in[2];
    const float* lin_w  = (const float*)d_in[3];
    const float* lin_b  = (const float*)d_in[4];
    float* out = (float*)d_out;

    // Fork a side branch for the full-output memset so it overlaps the
    // fold->logit->scan->compact chain; join before emit.
    cudaStream_t sz;
    cudaEvent_t evFork, evZero;
    cudaStreamCreateWithFlags(&sz, cudaStreamNonBlocking);
    cudaEventCreateWithFlags(&evFork, cudaEventDisableTiming);
    cudaEventCreateWithFlags(&evZero, cudaEventDisableTiming);

    cudaEventRecord(evFork, 0);
    cudaStreamWaitEvent(sz, evFork, 0);
    cudaMemsetAsync(d_out, 0, (size_t)out_size * sizeof(float), sz);
    cudaEventRecord(evZero, sz);

    fold_kernel<<<5, 256>>>(conv_w, conv_b, lin_w, lin_b);
    logit_kernel<<<BB * (TT / RPB), 256>>>(x);
    seq_scan_kernel<<<1, 32>>>();
    compact_kernel<<<BB, 256>>>();

    cudaStreamWaitEvent(0, evZero, 0);   // join memset branch before emit

    const size_t dense = (size_t)BB * TT * FEAT;
    int write_len = (out_size >= (int)(dense + BB)) ? 1 : 0;
    float* lens = out + dense;
    emit_kernel<<<dim3(BB, 256), FEAT>>>(x, out, lens, write_len);

    cudaEventDestroy(evFork);
    cudaEventDestroy(evZero);
    cudaStreamDestroy(sz);
}

// round 11
// speedup vs baseline: 1.0926x; 1.0926x over previous
#include <cuda_runtime.h>

#define BB   16
#define TT   4096
#define FEAT 256
#define KW   5
#define CH   64            // seq_scan chunk (steps)
#define GRP  16            // checkpoint group
#define NGRP (TT / GRP)    // 256 groups per batch

// Scratch (no allocations allowed).
__device__ float  g_weff[FEAT * KW];
__device__ float  g_bias;
__device__ float  g_p[BB * TT * KW];
__device__ float  g_alphas[BB * TT];     // [b][t] for emit/compact
__device__ float  g_alphasT[TT * BB];    // [t][b] for seq_scan (coalesced)
__device__ float4 g_accq4[(TT / 4) * BB]; // acc BEFORE step, 4 steps per float4: [(t>>2)*16+b]
__device__ int    g_ft[BB * TT];
__device__ int2   g_seg[BB * TT];
__device__ int    g_n[BB];
__device__ int    g_nofire[BB];

#define ACCB(t, b) (((const float*)g_accq4)[(((t) >> 2) * BB + (b)) * 4 + ((t) & 3)])

// ---------------------------------------------------------------------------
// Kernel 1: fold lin_w into conv_w  ->  w_eff[c,k] = sum_o lin_w[o]*conv_w[o,c,k]
// ---------------------------------------------------------------------------
__global__ void fold_kernel(const float* __restrict__ conv_w,
                            const float* __restrict__ conv_b,
                            const float* __restrict__ lin_w,
                            const float* __restrict__ lin_b) {
    int j = blockIdx.x * blockDim.x + threadIdx.x;   // j = c*KW + k
    if (j < FEAT * KW) {
        float s = 0.f;
#pragma unroll 4
        for (int o = 0; o < FEAT; ++o)
            s = fmaf(lin_w[o], conv_w[o * (FEAT * KW) + j], s);
        g_weff[j] = s;
    }
    if (blockIdx.x == 0) {
        __shared__ float sh[256];
        sh[threadIdx.x] = conv_b[threadIdx.x] * lin_w[threadIdx.x];
        __syncthreads();
        for (int ofs = 128; ofs > 0; ofs >>= 1) {
            if ((int)threadIdx.x < ofs) sh[threadIdx.x] += sh[threadIdx.x + ofs];
            __syncthreads();
        }
        if (threadIdx.x == 0) g_bias = sh[0] + lin_b[0];
    }
}

// ---------------------------------------------------------------------------
// Kernel 2: p[row][k] = dot(x[row,:], w_eff[:,k]) for k=0..4.
// ---------------------------------------------------------------------------
__global__ __launch_bounds__(256) void pk_kernel(const float* __restrict__ x) {
    int warp_global = (blockIdx.x * blockDim.x + threadIdx.x) >> 5;  // 0..8191
    int lane = threadIdx.x & 31;
    int c0 = lane * 4;

    float w[8][KW];
#pragma unroll
    for (int j = 0; j < 8; ++j) {
        int c = (j < 4) ? (c0 + j) : (c0 + 124 + j);
#pragma unroll
        for (int k = 0; k < KW; ++k) w[j][k] = g_weff[c * KW + k];
    }

    long row0 = (long)warp_global * 8;
    for (int r = 0; r < 8; ++r) {
        long row = row0 + r;
        const float4* r4 = (const float4*)(x + row * FEAT);
        float4 va = r4[lane];
        float4 vb = r4[lane + 32];
        float xs[8] = {va.x, va.y, va.z, va.w, vb.x, vb.y, vb.z, vb.w};
        float s[KW] = {0.f, 0.f, 0.f, 0.f, 0.f};
#pragma unroll
        for (int j = 0; j < 8; ++j)
#pragma unroll
            for (int k = 0; k < KW; ++k)
                s[k] = fmaf(xs[j], w[j][k], s[k]);
#pragma unroll
        for (int k = 0; k < KW; ++k)
#pragma unroll
            for (int ofs = 16; ofs > 0; ofs >>= 1)
                s[k] += __shfl_xor_sync(0xffffffffu, s[k], ofs);
        if (lane == 0) {
#pragma unroll
            for (int k = 0; k < KW; ++k) g_p[row * KW + k] = s[k];
        }
    }
}

// ---------------------------------------------------------------------------
// Kernel 3: alphas[b,t] = sigmoid( bias + sum_k p[b, t+k-2, k] )  (SAME pad)
// Writes both [b][t] and transposed [t][b] copies.
// ---------------------------------------------------------------------------
__global__ void alpha_kernel() {
    int i = blockIdx.x * blockDim.x + threadIdx.x;   // i = b*T + t
    if (i >= BB * TT) return;
    int t = i & (TT - 1);
    int b = i >> 12;
    float s = g_bias;
#pragma unroll
    for (int k = 0; k < KW; ++k) {
        int tt = t + k - 2;
        if (tt >= 0 && tt < TT) s += g_p[(long)(i + k - 2) * KW + k];
    }
    float v = 1.f / (1.f + expf(-s));
    g_alphas[i] = v;
    g_alphasT[t * BB + b] = v;
}

// ---------------------------------------------------------------------------
// Kernel 4: sequential alpha scan. 16 active lanes (one per batch), all 32
// lanes cooperate on staging. Chunks of 64 steps double-buffered in smem.
// ---------------------------------------------------------------------------
__global__ __launch_bounds__(32, 1) void seq_scan_kernel() {
    __shared__ float sa[2][CH * BB];          // 2 x 4KB
    const int lane = threadIdx.x;
    const int b = lane & 15;

    const float4* src = (const float4*)g_alphasT;

    {
        float4 v[8];
#pragma unroll
        for (int i = 0; i < 8; ++i) v[i] = src[lane + 32 * i];
#pragma unroll
        for (int i = 0; i < 8; ++i) ((float4*)sa[0])[lane + 32 * i] = v[i];
    }
    __syncwarp();

    float acc = 0.f;
    int buf = 0;
    float4* accq = g_accq4;

    for (int c = 0; c < TT / CH; ++c) {
        float4 pf[8];
        if (c + 1 < TT / CH) {
            const float4* s2 = src + (c + 1) * (CH * BB / 4);
#pragma unroll
            for (int i = 0; i < 8; ++i) pf[i] = s2[lane + 32 * i];
        }

        if (lane < 16) {
            const float* s = sa[buf] + b;
            float cur[16], nxt[16];
#pragma unroll
            for (int j = 0; j < 16; ++j) cur[j] = s[j * BB];
#pragma unroll
            for (int sub = 0; sub < CH / 16; ++sub) {
                if (sub + 1 < CH / 16) {
#pragma unroll
                    for (int j = 0; j < 16; ++j)
                        nxt[j] = s[(sub * 16 + 16 + j) * BB];
                }
                int qbase = (c * CH + sub * 16) >> 2;   // float4 group index
#pragma unroll
                for (int q = 0; q < 4; ++q) {
                    float4 av;
#pragma unroll
                    for (int j = 0; j < 4; ++j) {
                        float a = cur[q * 4 + j];
                        ((float*)&av)[j] = acc;
                        float acc_new = acc + a;
                        float a1 = 1.0f - acc;
                        float a2 = a - a1;
                        acc = (acc_new >= 1.0f) ? a2 : acc_new;
                    }
                    accq[(qbase + q) * BB + b] = av;
                }
#pragma unroll
                for (int j = 0; j < 16; ++j) cur[j] = nxt[j];
            }
        }

        if (c + 1 < TT / CH) {
            buf ^= 1;
            __syncwarp();
#pragma unroll
            for (int i = 0; i < 8; ++i)
                ((float4*)sa[buf])[lane + 32 * i] = pf[i];
            __syncwarp();
        }
    }
}

// ---------------------------------------------------------------------------
// Kernel 5: compaction. Recomputes fire = (acc_before + alpha >= 1) with the
// exact fp32 op the scan used, then prefix + scatter -> segment table.
// ---------------------------------------------------------------------------
__global__ __launch_bounds__(128) void compact_kernel(float* __restrict__ lens,
                                                      int write_len) {
    int b = blockIdx.x;
    int t = threadIdx.x;
    __shared__ int pre[129];
    __shared__ int tmp[128];

    unsigned m = 0u;
    {
        int base = t * 32;
        const float* ab = g_alphas + (size_t)b * TT + base;
        const float4* aq = g_accq4 + (base >> 2) * BB + b;
#pragma unroll
        for (int qq = 0; qq < 8; ++qq) {
            float4 v = aq[qq * BB];
            float accs[4] = {v.x, v.y, v.z, v.w};
#pragma unroll
            for (int j = 0; j < 4; ++j) {
                int i = qq * 4 + j;
                if (accs[j] + ab[i] >= 1.0f) m |= (1u << i);
            }
        }
    }
    int cnt = __popc(m);

    tmp[t] = cnt;
    __syncthreads();
    for (int ofs = 1; ofs < 128; ofs <<= 1) {
        int v = (t >= ofs) ? tmp[t - ofs] : 0;
        __syncthreads();
        tmp[t] += v;
        __syncthreads();
    }
    pre[t + 1] = tmp[t];
    if (t == 0) pre[0] = 0;
    __syncthreads();

    int n = pre[128];
    const int wbase = b * TT;

    int rank = pre[t];
    unsigned mm = m;
    while (mm) {
        int i = __ffs(mm) - 1;
        mm &= mm - 1;
        g_ft[wbase + rank] = t * 32 + i;
        ++rank;
    }
    __syncthreads();

    if (n == 0) {
        if (t == 0) {
            g_ft[wbase] = TT - 1;
            g_seg[wbase] = make_int2(-1, TT - 1);
            g_n[b] = 1;
            g_nofire[b] = 1;
            if (write_len) lens[b] = 1.0f;
        }
        return;
    }

    for (int j = t; j < n; j += 128) {
        int s = (j == 0) ? -1 : g_ft[wbase + j - 1];
        g_seg[wbase + j] = make_int2(s, g_ft[wbase + j]);
    }
    if (t == 0) {
        g_n[b] = n;
        g_nofire[b] = 0;
        if (write_len) lens[b] = (float)n;
    }
}

// ---------------------------------------------------------------------------
// Kernel 6: fused emission + tail zero — R10: 4x more blocks (gridDim.y=1024,
// 4 j per block) and software-pipelined segment descriptors so the next j's
// seg/weights loads overlap the current segment's accumulation. All fp ops
// on the value path identical to R5.
// ---------------------------------------------------------------------------
__global__ __launch_bounds__(FEAT) void emit_kernel(const float* __restrict__ x,
                                                    float* __restrict__ out) {
    int b = blockIdx.x;
    int d = threadIdx.x;
    int n = g_n[b];
    int nofire = g_nofire[b];
    const float* xb = x + (size_t)b * TT * FEAT;
    const float* ab = g_alphas + (size_t)b * TT;
    const int wbase = b * TT;
    float* ob = out + (size_t)b * TT * FEAT;
    const int stride = gridDim.y;

    int j = blockIdx.y;
    // prefetch first descriptor
    int2 se = (j < n) ? g_seg[wbase + j] : make_int2(0, 0);

    for (; j < TT; ) {
        int jn = j + stride;
        if (j >= n) {
            // tail zero; descriptors irrelevant
            ob[(size_t)j * FEAT + d] = 0.f;
            j = jn;
            if (j < n) se = g_seg[wbase + j];   // (unreachable: j grows) safe
            continue;
        }
        // prefetch next descriptor while we accumulate this segment
        int2 se_nxt = (jn < n) ? g_seg[wbase + jn] : make_int2(0, 0);

        float accv = 0.f;
        int u0 = 0;
        if (se.x >= 0) {
            float a2 = ab[se.x] - (1.0f - ACCB(se.x, b));
            accv = a2 * xb[(size_t)se.x * FEAT + d];
            u0 = se.x + 1;
        }
        for (int u = u0; u < se.y; ++u)
            accv = fmaf(ab[u], xb[(size_t)u * FEAT + d], accv);
        float we = nofire ? ab[se.y] : (1.0f - ACCB(se.y, b));
        accv = fmaf(we, xb[(size_t)se.y * FEAT + d], accv);
        ob[(size_t)j * FEAT + d] = accv;

        se = se_nxt;
        j = jn;
    }
}

// ---------------------------------------------------------------------------
extern "C" void kernel_launch(void* const* d_in, const int* in_sizes, int n_in,
                              void* d_out, int out_size) {
    const float* x      = (const float*)d_in[0];
    const float* conv_w = (const float*)d_in[1];
    const float* conv_b = (const float*)d_in[2];
    const float* lin_w  = (const float*)d_in[3];
    const float* lin_b  = (const float*)d_in[4];
    float* out = (float*)d_out;

    const size_t dense = (size_t)BB * TT * FEAT;
    if ((size_t)out_size > dense)
        cudaMemsetAsync(out + dense, 0, ((size_t)out_size - dense) * sizeof(float), 0);

    fold_kernel<<<5, 256>>>(conv_w, conv_b, lin_w, lin_b);
    pk_kernel<<<1024, 256>>>(x);
    alpha_kernel<<<(BB * TT + 255) / 256, 256>>>();

    seq_scan_kernel<<<1, 32>>>();

    int write_len = (out_size >= (int)(dense + BB)) ? 1 : 0;
    float* lens = out + dense;
    compact_kernel<<<BB, 128>>>(lens, write_len);

    emit_kernel<<<dim3(BB, 1024), FEAT>>>(x, out);
}